// round 14
// baseline (speedup 1.0000x reference)
#include <cuda_runtime.h>

#define NN 20000      // nodes
#define NE 100000     // edges
#define NF 64         // node feature dim (in) — 64 for every layer here
#define EFD 32        // edge feature dim
#define FH 128        // heads * out_dim = 2*64
#define NH 2          // heads
#define DH 64         // out dim per head

// ---------------- scratch (device globals) ----------------------------------
__device__ __align__(16) float g_elb[2][NN * NH]; // double-buffered el
__device__ __align__(16) float g_erb[2][NN * NH]; // double-buffered er
__device__ __align__(16) float g_h [NN * NF];
__device__ __align__(16) float g_h2[NN * NF];
__device__ __align__(16) float g_Wp[NF * FH];     // W_e2d^T @ Wn_dec0
__device__ __align__(16) float g_efs[NE * EFD];   // ef rows in CSR(sorted) order
__device__ __align__(8)  float g_eeall[4][NE * NH]; // ee per layer, CSR order
__device__ int g_srcs[NE];                        // src in CSR order
// reduced attention weights per layer
__device__ float g_redl[4][NH * NF];
__device__ float g_redr[4][NH * NF];
__device__ float g_rede[4][NH * EFD];
// CSR over DEGREE-SORTED node order
__device__ int g_deg[NN];        // zero-init at load; scan re-zeroes each call
__device__ int g_off[NN + 1];    // offsets by sorted position
__device__ int g_cur[NN];        // scatter cursor by ORIGINAL node id
__device__ int g_perm[NN];       // sorted position -> original node id

struct PrepParams {
    const float *Wn[4], *We[4], *al[4], *ar[4], *ae[4];
    const float* We2d;
};

// ================= pre1: hist + wfuse + prep (fused) ========================
#define B_HIST 391     // ceil(NE/256)
#define B_WF   32      // NF*FH/256
#define B_PREP 12      // 4 layers * 3 matrices
__global__ __launch_bounds__(256) void pre1_kernel(
        const int* __restrict__ dst, PrepParams pp)
{
    const int t = threadIdx.x;
    const int b = blockIdx.x;
    if (b < B_HIST) {                              // ---- histogram
        const int e = b * 256 + t;
        if (e < NE) atomicAdd(&g_deg[dst[e]], 1);
    } else if (b < B_HIST + B_WF) {                // ---- Wp = W_e2d^T @ Wn_dec0
        const int i = (b - B_HIST) * 256 + t;      // m*128 + c
        const int m = i >> 7, c = i & 127;
        float v = 0.f;
#pragma unroll
        for (int k = 0; k < NF; k++)
            v = fmaf(pp.We2d[k * NF + m], pp.Wn[2][k * FH + c], v);
        g_Wp[m * FH + c] = v;
    } else {                                       // ---- reduced attn weights
        const int bid2 = b - B_HIST - B_WF;
        const int lid = bid2 / 3, mat = bid2 % 3;
        __shared__ float stt[128];
        if (mat < 2) {                             // redl / redr
            const float* a = mat ? pp.ar[lid] : pp.al[lid];
            float v = 0.f;
            if (t < 128) {
                const int h = t >> 6, k = t & 63;
#pragma unroll
                for (int d = 0; d < DH; d++)
                    v = fmaf(pp.Wn[lid][k * FH + h * DH + d], a[h * DH + d], v);
                if (lid == 2) stt[t] = v;          // two-step for dec0 (e2d fused)
                else (mat ? g_redr : g_redl)[lid][(t >> 6) * NF + (t & 63)] = v;
            }
            if (lid == 2) {
                __syncthreads();
                if (t < 128) {
                    const int h = t >> 6, m = t & 63;
                    float w = 0.f;
#pragma unroll
                    for (int k = 0; k < NF; k++)
                        w = fmaf(pp.We2d[k * NF + m], stt[h * 64 + k], w);
                    (mat ? g_redr : g_redl)[2][h * NF + m] = w;
                }
            }
        } else if (t < NH * EFD) {                 // rede
            const int h = t >> 5, k = t & 31;
            float v = 0.f;
#pragma unroll
            for (int d = 0; d < DH; d++)
                v = fmaf(pp.We[lid][k * FH + h * DH + d], pp.ae[lid][h * DH + d], v);
            g_rede[lid][h * EFD + k] = v;
        }
    }
}

// ================= scan: degree counting sort + prefix sum ===================
// Produces: g_perm (sorted pos -> node), g_off (offsets by sorted pos),
//           g_cur (scatter cursor by original node)
#define SCAN_T 1024
#define CHUNK 20
#define NBIN 128
#define NSUB 16
__global__ __launch_bounds__(SCAN_T) void scan_kernel()
{
    extern __shared__ int si[];
    int* sdeg  = si;                    // NN: degree by node, later rank by node
    int* sdeg2 = si + NN;               // NN: degree by sorted pos, later prefix
    int* sp    = si + 2 * NN;           // SCAN_T
    int* sb    = si + 2 * NN + SCAN_T;  // SCAN_T
    int* bins  = si + 2 * NN + 2 * SCAN_T;          // NBIN
    int* sub   = si + 2 * NN + 2 * SCAN_T + NBIN;   // NSUB*NBIN
    const int t = threadIdx.x;
    const int wsub = (t >> 5) & (NSUB - 1);

    for (int i = t; i < NN; i += SCAN_T) { sdeg[i] = g_deg[i]; g_deg[i] = 0; }
    for (int i = t; i < NSUB * NBIN; i += SCAN_T) sub[i] = 0;
    __syncthreads();
    // degree histogram (16 sub-histograms to cut contention)
    for (int i = t; i < NN; i += SCAN_T) {
        int d = sdeg[i]; if (d > NBIN - 1) d = NBIN - 1;
        atomicAdd(&sub[wsub * NBIN + d], 1);
    }
    __syncthreads();
    if (t < NBIN) {
        int v = 0;
#pragma unroll
        for (int w = 0; w < NSUB; w++) v += sub[w * NBIN + t];
        bins[t] = v;
    }
    __syncthreads();
    if (t == 0) {                        // serial prefix over 128 bins
        int acc = 0;
        for (int k = 0; k < NBIN; k++) { int v = bins[k]; bins[k] = acc; acc += v; }
    }
    __syncthreads();
    // scatter: rank via atomic bump; perm + sorted degrees
    for (int i = t; i < NN; i += SCAN_T) {
        int d = sdeg[i]; int dc = (d > NBIN - 1) ? NBIN - 1 : d;
        const int r = atomicAdd(&bins[dc], 1);
        g_perm[r] = i;
        sdeg2[r] = d;
        sdeg[i] = r;                     // rank by node
    }
    __syncthreads();
    // chunked exclusive scan of sorted degrees
    const int base = t * CHUNK;
    int sum = 0;
#pragma unroll
    for (int q = 0; q < CHUNK; q++) {
        const int idx = base + q;
        if (idx < NN) {
            const int d = sdeg2[idx];
            sdeg2[idx] = sum;
            sum += d;
        }
    }
    sp[t] = sum;
    __syncthreads();
    for (int o = 1; o < SCAN_T; o <<= 1) {
        int v = 0;
        if (t >= o) v = sp[t - o];
        __syncthreads();
        if (t >= o) sp[t] += v;
        __syncthreads();
    }
    sb[t] = sp[t] - sum;
    __syncthreads();
    for (int r = t; r < NN; r += SCAN_T)
        g_off[r] = sdeg2[r] + sb[r / CHUNK];
    if (t == SCAN_T - 1) g_off[NN] = sp[SCAN_T - 1];
    __syncthreads();
    for (int i = t; i < NN; i += SCAN_T) {
        const int r = sdeg[i];
        g_cur[i] = sdeg2[r] + sb[r / CHUNK];
    }
}
#define SCAN_SMEM ((2 * NN + 2 * SCAN_T + NBIN + NSUB * NBIN) * 4)

// ================= pre2: scatterF + layer-0 el/er (fused) ===================
#define B_SCAT 391     // ceil(NE/256)
#define B_NA   313     // ceil(NN/64)
__global__ __launch_bounds__(256) void pre2_kernel(
        const int* __restrict__ dst, const int* __restrict__ src,
        const float* __restrict__ ef, const float* __restrict__ x)
{
    __shared__ float smf[64 * 65];
    const int t = threadIdx.x;
    const int b = blockIdx.x;
    if (b < B_SCAT) {
        // ---- scatter + gather + 4-layer ee
        float* srd = smf;                       // [4][NH*EFD] = 256
        if (t < 4 * NH * EFD) srd[t] = ((const float*)g_rede)[t];
        __syncthreads();
        const int e = b * 256 + t;
        if (e >= NE) return;
        const int pos = atomicAdd(&g_cur[dst[e]], 1);
        g_srcs[pos] = src[e];
        float r[EFD];
#pragma unroll
        for (int q = 0; q < EFD / 4; q++) {
            const float4 v = __ldg((const float4*)&ef[(size_t)e * EFD + q * 4]);
            r[q * 4 + 0] = v.x; r[q * 4 + 1] = v.y;
            r[q * 4 + 2] = v.z; r[q * 4 + 3] = v.w;
            *(float4*)&g_efs[(size_t)pos * EFD + q * 4] = v;
        }
#pragma unroll
        for (int lid = 0; lid < 4; lid++) {
            float v0 = 0.f, v1 = 0.f;
#pragma unroll
            for (int k = 0; k < EFD; k++) {
                v0 = fmaf(r[k], srd[lid * 64 + k], v0);
                v1 = fmaf(r[k], srd[lid * 64 + EFD + k], v1);
            }
            *(float2*)&g_eeall[lid][(size_t)pos * NH] = make_float2(v0, v1);
        }
    } else {
        // ---- layer-0 el/er for 64 nodes (by ORIGINAL node id)
        const int n0 = (b - B_SCAT) * 64;
        for (int i = t; i < 64 * NF; i += 256) {
            const int row = i >> 6, col = i & 63;
            const int n = n0 + row;
            smf[row * 65 + col] = (n < NN) ? x[(size_t)n * NF + col] : 0.f;
        }
        __syncthreads();
        const int type = t >> 7, h = (t >> 6) & 1, i = t & 63;
        const int n = n0 + i;
        if (n < NN) {
            const float* rd = (type ? g_redr : g_redl)[0] + h * NF;
            float v = 0.f;
#pragma unroll
            for (int k = 0; k < NF; k++) v = fmaf(smf[i * 65 + k], rd[k], v);
            (type ? g_erb : g_elb)[0][n * NH + h] = v;
        }
    }
}

// ================= fused per-layer kernel ====================================
// 256 threads, 16 SORTED positions/block (degree-uniform after counting sort).
// Phase A: half-warp per node, 2 edges/iter, NEXT pair's src indices
//          prefetched (cuts the loop-carried srcs->x chain to one L2 trip).
// Phase B: 8-row x 1-col register tiles, 2 row-groups share each weight load.
// Phase C: head-mean -> hout (rows via g_perm); next-layer el/er epilogue.
#define STS_ 129                   // st row stride
__global__ __launch_bounds__(256) void layer_kernel(
        const float* __restrict__ x,
        const float* __restrict__ Wn, const float* __restrict__ We,
        const float* __restrict__ b,
        const float* __restrict__ el_in, const float* __restrict__ er_in,
        float* __restrict__ el_out, float* __restrict__ er_out,
        int lid, int last, float* __restrict__ hout)
{
    __shared__ __align__(16) float sV[192 * 16];  // [k][i]; k<128 xs(h*64+kk), k>=128 us
    __shared__ float st[16 * STS_];               // [i][c]
    __shared__ int sperm[16];

    const int t = threadIdx.x;
    const int wid = t >> 5, lane = t & 31;
    const int half = lane >> 4, s = lane & 15;
    const int i = wid * 2 + half;                 // block-local sorted slot 0..15
    const int n0 = blockIdx.x * 16;               // sorted position base
    if (t < 16) sperm[t] = g_perm[n0 + t];
    const float* eep = g_eeall[lid];

    const int n = g_perm[n0 + i];                 // actual node id
    const float2 er2 = *(const float2*)&er_in[n * NH];
    const int start = g_off[n0 + i];
    const int deg = g_off[n0 + i + 1] - start;
    const int dother = __shfl_xor_sync(0xffffffffu, deg, 16);
    const int degmax = (deg > dother) ? deg : dother;

    float4 xa0 = make_float4(0.f, 0.f, 0.f, 0.f);   // head-0 weighted x sums
    float4 xa1 = make_float4(0.f, 0.f, 0.f, 0.f);   // head-1
    float2 ua0 = make_float2(0.f, 0.f);
    float2 ua1 = make_float2(0.f, 0.f);
    float s0 = 0.f, s1 = 0.f;

    // clamped edge index for slot o (keeps loads in-bounds for inactive lanes)
    auto cj = [&](int o) {
        if (o > deg - 1) o = deg - 1;
        if (o < 0) o = 0;
        int j = start + o;
        return (j > NE - 1) ? NE - 1 : j;
    };

    int j0 = cj(0), j1 = cj(1);
    int sn0 = g_srcs[j0], sn1 = g_srcs[j1];        // prefetched

    for (int jj = 0; jj < degmax; jj += 2) {
        const bool a0 = (jj < deg), a1 = (jj + 1 < deg);
        const int cj0 = j0, cj1 = j1, csn0 = sn0, csn1 = sn1;
        if (jj + 2 < degmax) {                     // prefetch next pair's srcs
            j0 = cj(jj + 2); j1 = cj(jj + 3);
            sn0 = g_srcs[j0]; sn1 = g_srcs[j1];
        }

        const float2 ee0 = *(const float2*)&eep[(size_t)cj0 * NH];
        const float2 ee1 = *(const float2*)&eep[(size_t)cj1 * NH];
        const float2 eA = *(const float2*)&el_in[csn0 * NH];
        const float2 eB = *(const float2*)&el_in[csn1 * NH];
        const float4 xv0 = __ldg((const float4*)&x[(size_t)csn0 * NF + s * 4]);
        const float4 xv1 = __ldg((const float4*)&x[(size_t)csn1 * NF + s * 4]);
        const float2 ev0 = *(const float2*)&g_efs[(size_t)cj0 * EFD + s * 2];
        const float2 ev1 = *(const float2*)&g_efs[(size_t)cj1 * EFD + s * 2];

        float l00 = eA.x + er2.x + ee0.x, l01 = eA.y + er2.y + ee0.y;
        float l10 = eB.x + er2.x + ee1.x, l11 = eB.y + er2.y + ee1.y;
        l00 = (l00 > 0.f) ? l00 : 0.2f * l00;
        l01 = (l01 > 0.f) ? l01 : 0.2f * l01;
        l10 = (l10 > 0.f) ? l10 : 0.2f * l10;
        l11 = (l11 > 0.f) ? l11 : 0.2f * l11;
        const float p00 = a0 ? __expf(l00) : 0.f;
        const float p01 = a0 ? __expf(l01) : 0.f;
        const float p10 = a1 ? __expf(l10) : 0.f;
        const float p11 = a1 ? __expf(l11) : 0.f;
        s0 += p00 + p10; s1 += p01 + p11;

        xa0.x = fmaf(xv0.x, p00, fmaf(xv1.x, p10, xa0.x));
        xa0.y = fmaf(xv0.y, p00, fmaf(xv1.y, p10, xa0.y));
        xa0.z = fmaf(xv0.z, p00, fmaf(xv1.z, p10, xa0.z));
        xa0.w = fmaf(xv0.w, p00, fmaf(xv1.w, p10, xa0.w));
        xa1.x = fmaf(xv0.x, p01, fmaf(xv1.x, p11, xa1.x));
        xa1.y = fmaf(xv0.y, p01, fmaf(xv1.y, p11, xa1.y));
        xa1.z = fmaf(xv0.z, p01, fmaf(xv1.z, p11, xa1.z));
        xa1.w = fmaf(xv0.w, p01, fmaf(xv1.w, p11, xa1.w));
        ua0.x = fmaf(ev0.x, p00, fmaf(ev1.x, p10, ua0.x));
        ua0.y = fmaf(ev0.y, p00, fmaf(ev1.y, p10, ua0.y));
        ua1.x = fmaf(ev0.x, p01, fmaf(ev1.x, p11, ua1.x));
        ua1.y = fmaf(ev0.y, p01, fmaf(ev1.y, p11, ua1.y));
    }

    const float inv0 = (s0 > 0.f) ? 1.f / s0 : 0.f;   // deg-0 -> msg = 0
    const float inv1 = (s1 > 0.f) ? 1.f / s1 : 0.f;
    sV[(4 * s + 0) * 16 + i] = xa0.x * inv0;
    sV[(4 * s + 1) * 16 + i] = xa0.y * inv0;
    sV[(4 * s + 2) * 16 + i] = xa0.z * inv0;
    sV[(4 * s + 3) * 16 + i] = xa0.w * inv0;
    sV[(64 + 4 * s + 0) * 16 + i] = xa1.x * inv1;
    sV[(64 + 4 * s + 1) * 16 + i] = xa1.y * inv1;
    sV[(64 + 4 * s + 2) * 16 + i] = xa1.z * inv1;
    sV[(64 + 4 * s + 3) * 16 + i] = xa1.w * inv1;
    sV[(128 + 2 * s + 0) * 16 + i] = ua0.x * inv0;
    sV[(128 + 2 * s + 1) * 16 + i] = ua0.y * inv0;
    sV[(160 + 2 * s + 0) * 16 + i] = ua1.x * inv1;
    sV[(160 + 2 * s + 1) * 16 + i] = ua1.y * inv1;
    __syncthreads();

    // -------- Phase B: 8-row x 1-col tiles; 2 row-groups --------
    {
        const int c = t & 127, h = c >> 6;
        const int rb = (t >> 7) * 8;              // row base: 0 or 8
        float acc[8];
#pragma unroll
        for (int r = 0; r < 8; r++) acc[r] = 0.f;

        const float* sVx = sV + (h * 64) * 16 + rb;
#pragma unroll 4
        for (int kk = 0; kk < NF; kk++) {
            const float w = __ldg(&Wn[kk * FH + c]);
            const float4 v0 = *(const float4*)&sVx[kk * 16];
            const float4 v1 = *(const float4*)&sVx[kk * 16 + 4];
            acc[0] = fmaf(v0.x, w, acc[0]); acc[1] = fmaf(v0.y, w, acc[1]);
            acc[2] = fmaf(v0.z, w, acc[2]); acc[3] = fmaf(v0.w, w, acc[3]);
            acc[4] = fmaf(v1.x, w, acc[4]); acc[5] = fmaf(v1.y, w, acc[5]);
            acc[6] = fmaf(v1.z, w, acc[6]); acc[7] = fmaf(v1.w, w, acc[7]);
        }
        const float* sVu = sV + (128 + h * 32) * 16 + rb;
#pragma unroll 4
        for (int kk = 0; kk < EFD; kk++) {
            const float w = __ldg(&We[kk * FH + c]);
            const float4 v0 = *(const float4*)&sVu[kk * 16];
            const float4 v1 = *(const float4*)&sVu[kk * 16 + 4];
            acc[0] = fmaf(v0.x, w, acc[0]); acc[1] = fmaf(v0.y, w, acc[1]);
            acc[2] = fmaf(v0.z, w, acc[2]); acc[3] = fmaf(v0.w, w, acc[3]);
            acc[4] = fmaf(v1.x, w, acc[4]); acc[5] = fmaf(v1.y, w, acc[5]);
            acc[6] = fmaf(v1.z, w, acc[6]); acc[7] = fmaf(v1.w, w, acc[7]);
        }
        const float bc = __ldg(&b[c]);
#pragma unroll
        for (int r = 0; r < 8; r++)
            st[(rb + r) * STS_ + c] = acc[r] + bc;
    }
    __syncthreads();

    // -------- Phase C: head mean -> hout rows via perm (4 per thread) -------
#pragma unroll
    for (int rep = 0; rep < 4; rep++) {
        const int idx = rep * 256 + t;
        const int ii = idx >> 6, d = idx & 63;
        hout[(size_t)sperm[ii] * DH + d] =
            0.5f * (st[ii * STS_ + d] + st[ii * STS_ + DH + d]);
    }
    // next-layer el/er (64 tasks: type x head x 16 nodes)
    if (!last && t < 64) {
        const int type = t >> 5, hh = (t >> 4) & 1, ii = t & 15;
        const float* rd = (type ? g_redr : g_redl)[lid + 1] + hh * NF;
        float v = 0.f;
#pragma unroll
        for (int d = 0; d < DH; d++)
            v = fmaf(0.5f * (st[ii * STS_ + d] + st[ii * STS_ + DH + d]), rd[d], v);
        (type ? er_out : el_out)[sperm[ii] * NH + hh] = v;
    }
}

// ---------------- host-side driver ------------------------------------------
extern "C" void kernel_launch(void* const* d_in, const int* in_sizes, int n_in,
                              void* d_out, int out_size)
{
    const float* x   = (const float*)d_in[0];
    const float* e   = (const float*)d_in[1];
    const int*   src = (const int*)  d_in[2];
    const int*   dst = (const int*)  d_in[3];

    // Only the LAST snapshot contributes to the output (decoded[-1]).
    const int S = in_sizes[0] / (NN * NF);
    const float* xs = x   + (size_t)(S - 1) * NN * NF;
    const float* es = e   + (size_t)(S - 1) * NE * EFD;
    const int*   ss = src + (size_t)(S - 1) * NE;
    const int*   ds = dst + (size_t)(S - 1) * NE;

    void *ph = nullptr, *ph2 = nullptr, *pwp = nullptr, *pel = nullptr, *per = nullptr;
    cudaGetSymbolAddress(&ph,  g_h);
    cudaGetSymbolAddress(&ph2, g_h2);
    cudaGetSymbolAddress(&pwp, g_Wp);
    cudaGetSymbolAddress(&pel, g_elb);
    cudaGetSymbolAddress(&per, g_erb);
    float* h  = (float*)ph;
    float* h2 = (float*)ph2;
    const float* Wp = (const float*)pwp;
    float* elb[2] = { (float*)pel, (float*)pel + NN * NH };
    float* erb[2] = { (float*)per, (float*)per + NN * NH };

    cudaFuncSetAttribute(scan_kernel, cudaFuncAttributeMaxDynamicSharedMemorySize,
                         SCAN_SMEM);

    // Input order (setup_inputs dict insertion order):
    //   0:x 1:e 2:src 3:dst, 4..9:enc0{Wn,We,al,ar,ae,b}, 10..15:enc1,
    //   16..21:dec0, 22..27:dec1, 28:W_e2d
    const float* P[29];
    for (int i = 4; i <= 28; i++) P[i] = (const float*)d_in[i];

    PrepParams pp;
    pp.Wn[0] = P[4];  pp.We[0] = P[5];  pp.al[0] = P[6];  pp.ar[0] = P[7];  pp.ae[0] = P[8];
    pp.Wn[1] = P[10]; pp.We[1] = P[11]; pp.al[1] = P[12]; pp.ar[1] = P[13]; pp.ae[1] = P[14];
    pp.Wn[2] = P[16]; pp.We[2] = P[17]; pp.al[2] = P[18]; pp.ar[2] = P[19]; pp.ae[2] = P[20];
    pp.Wn[3] = P[22]; pp.We[3] = P[23]; pp.al[3] = P[24]; pp.ar[3] = P[25]; pp.ae[3] = P[26];
    pp.We2d = P[28];

    pre1_kernel<<<B_HIST + B_WF + B_PREP, 256>>>(ds, pp);
    scan_kernel<<<1, SCAN_T, SCAN_SMEM>>>();
    pre2_kernel<<<B_SCAT + B_NA, 256>>>(ds, ss, es, xs);

    layer_kernel<<<NN / 16, 256>>>(xs, P[4],  P[5],  P[9],
                                   elb[0], erb[0], elb[1], erb[1], 0, 0, h);
    layer_kernel<<<NN / 16, 256>>>(h,  P[10], P[11], P[15],
                                   elb[1], erb[1], elb[0], erb[0], 1, 0, h2);
    layer_kernel<<<NN / 16, 256>>>(h2, Wp,    P[17], P[21],
                                   elb[0], erb[0], elb[1], erb[1], 2, 0, h);
    layer_kernel<<<NN / 16, 256>>>(h,  P[22], P[23], P[27],
                                   elb[1], erb[1], elb[0], erb[0], 3, 1, (float*)d_out);
}

// round 15
// speedup vs baseline: 1.0340x; 1.0340x over previous
#include <cuda_runtime.h>

#define NN 20000      // nodes
#define NE 100000     // edges
#define NF 64         // node feature dim (in) — 64 for every layer here
#define EFD 32        // edge feature dim
#define FH 128        // heads * out_dim = 2*64
#define NH 2          // heads
#define DH 64         // out dim per head

// ---------------- scratch (device globals) ----------------------------------
__device__ __align__(16) float g_elb[2][NN * NH]; // double-buffered el
__device__ __align__(16) float g_erb[2][NN * NH]; // double-buffered er
__device__ __align__(16) float g_h [NN * NF];
__device__ __align__(16) float g_h2[NN * NF];
__device__ __align__(16) float g_Wp[NF * FH];     // W_e2d^T @ Wn_dec0
__device__ __align__(16) float g_efs[NE * EFD];   // ef rows in CSR(sorted) order
__device__ __align__(8)  float g_eeall[4][NE * NH]; // ee per layer, CSR order
__device__ int g_srcs[NE];                        // src in CSR order
// reduced attention weights per layer
__device__ float g_redl[4][NH * NF];
__device__ float g_redr[4][NH * NF];
__device__ float g_rede[4][NH * EFD];
// CSR over DESCENDING-degree-sorted node order
__device__ int g_deg[NN];        // zero-init at load; scan re-zeroes each call
__device__ int g_off[NN + 1];    // offsets by sorted position
__device__ int g_cur[NN];        // scatter cursor by ORIGINAL node id
__device__ int g_perm[NN];       // sorted position -> original node id

struct PrepParams {
    const float *Wn[4], *We[4], *al[4], *ar[4], *ae[4];
    const float* We2d;
};

// ================= pre1: hist + wfuse + prep (fused) ========================
#define B_HIST 391     // ceil(NE/256)
#define B_WF   32      // NF*FH/256
#define B_PREP 12      // 4 layers * 3 matrices
__global__ __launch_bounds__(256) void pre1_kernel(
        const int* __restrict__ dst, PrepParams pp)
{
    const int t = threadIdx.x;
    const int b = blockIdx.x;
    if (b < B_HIST) {                              // ---- histogram
        const int e = b * 256 + t;
        if (e < NE) atomicAdd(&g_deg[dst[e]], 1);
    } else if (b < B_HIST + B_WF) {                // ---- Wp = W_e2d^T @ Wn_dec0
        const int i = (b - B_HIST) * 256 + t;      // m*128 + c
        const int m = i >> 7, c = i & 127;
        float v = 0.f;
#pragma unroll
        for (int k = 0; k < NF; k++)
            v = fmaf(pp.We2d[k * NF + m], pp.Wn[2][k * FH + c], v);
        g_Wp[m * FH + c] = v;
    } else {                                       // ---- reduced attn weights
        const int bid2 = b - B_HIST - B_WF;
        const int lid = bid2 / 3, mat = bid2 % 3;
        __shared__ float stt[128];
        if (mat < 2) {                             // redl / redr
            const float* a = mat ? pp.ar[lid] : pp.al[lid];
            float v = 0.f;
            if (t < 128) {
                const int h = t >> 6, k = t & 63;
#pragma unroll
                for (int d = 0; d < DH; d++)
                    v = fmaf(pp.Wn[lid][k * FH + h * DH + d], a[h * DH + d], v);
                if (lid == 2) stt[t] = v;          // two-step for dec0 (e2d fused)
                else (mat ? g_redr : g_redl)[lid][(t >> 6) * NF + (t & 63)] = v;
            }
            if (lid == 2) {
                __syncthreads();
                if (t < 128) {
                    const int h = t >> 6, m = t & 63;
                    float w = 0.f;
#pragma unroll
                    for (int k = 0; k < NF; k++)
                        w = fmaf(pp.We2d[k * NF + m], stt[h * 64 + k], w);
                    (mat ? g_redr : g_redl)[2][h * NF + m] = w;
                }
            }
        } else if (t < NH * EFD) {                 // rede
            const int h = t >> 5, k = t & 31;
            float v = 0.f;
#pragma unroll
            for (int d = 0; d < DH; d++)
                v = fmaf(pp.We[lid][k * FH + h * DH + d], pp.ae[lid][h * DH + d], v);
            g_rede[lid][h * EFD + k] = v;
        }
    }
}

// ================= scan: DESCENDING degree counting sort + prefix sum ========
// Produces: g_perm (sorted pos -> node, heaviest first), g_off, g_cur
#define SCAN_T 1024
#define CHUNK 20
#define NBIN 128
#define NSUB 16
__global__ __launch_bounds__(SCAN_T) void scan_kernel()
{
    extern __shared__ int si[];
    int* sdeg  = si;                    // NN: degree by node, later rank by node
    int* sdeg2 = si + NN;               // NN: degree by sorted pos, later prefix
    int* sp    = si + 2 * NN;           // SCAN_T
    int* sb    = si + 2 * NN + SCAN_T;  // SCAN_T
    int* bins  = si + 2 * NN + 2 * SCAN_T;          // NBIN
    int* sub   = si + 2 * NN + 2 * SCAN_T + NBIN;   // NSUB*NBIN
    const int t = threadIdx.x;
    const int wsub = (t >> 5) & (NSUB - 1);

    for (int i = t; i < NN; i += SCAN_T) { sdeg[i] = g_deg[i]; g_deg[i] = 0; }
    for (int i = t; i < NSUB * NBIN; i += SCAN_T) sub[i] = 0;
    __syncthreads();
    // degree histogram over DESCENDING bin index (NBIN-1-d)
    for (int i = t; i < NN; i += SCAN_T) {
        int d = sdeg[i]; if (d > NBIN - 1) d = NBIN - 1;
        atomicAdd(&sub[wsub * NBIN + (NBIN - 1 - d)], 1);
    }
    __syncthreads();
    if (t < NBIN) {
        int v = 0;
#pragma unroll
        for (int w = 0; w < NSUB; w++) v += sub[w * NBIN + t];
        bins[t] = v;
    }
    __syncthreads();
    if (t == 0) {                        // serial prefix over 128 bins
        int acc = 0;
        for (int k = 0; k < NBIN; k++) { int v = bins[k]; bins[k] = acc; acc += v; }
    }
    __syncthreads();
    // scatter: rank via atomic bump; perm + sorted degrees (heaviest first)
    for (int i = t; i < NN; i += SCAN_T) {
        int d = sdeg[i]; int dc = (d > NBIN - 1) ? NBIN - 1 : d;
        const int r = atomicAdd(&bins[NBIN - 1 - dc], 1);
        g_perm[r] = i;
        sdeg2[r] = d;
        sdeg[i] = r;                     // rank by node
    }
    __syncthreads();
    // chunked exclusive scan of sorted degrees
    const int base = t * CHUNK;
    int sum = 0;
#pragma unroll
    for (int q = 0; q < CHUNK; q++) {
        const int idx = base + q;
        if (idx < NN) {
            const int d = sdeg2[idx];
            sdeg2[idx] = sum;
            sum += d;
        }
    }
    sp[t] = sum;
    __syncthreads();
    for (int o = 1; o < SCAN_T; o <<= 1) {
        int v = 0;
        if (t >= o) v = sp[t - o];
        __syncthreads();
        if (t >= o) sp[t] += v;
        __syncthreads();
    }
    sb[t] = sp[t] - sum;
    __syncthreads();
    for (int r = t; r < NN; r += SCAN_T)
        g_off[r] = sdeg2[r] + sb[r / CHUNK];
    if (t == SCAN_T - 1) g_off[NN] = sp[SCAN_T - 1];
    __syncthreads();
    for (int i = t; i < NN; i += SCAN_T) {
        const int r = sdeg[i];
        g_cur[i] = sdeg2[r] + sb[r / CHUNK];
    }
}
#define SCAN_SMEM ((2 * NN + 2 * SCAN_T + NBIN + NSUB * NBIN) * 4)

// ================= pre2: scatterF + layer-0 el/er (fused) ===================
#define B_SCAT 391     // ceil(NE/256)
#define B_NA   313     // ceil(NN/64)
__global__ __launch_bounds__(256) void pre2_kernel(
        const int* __restrict__ dst, const int* __restrict__ src,
        const float* __restrict__ ef, const float* __restrict__ x)
{
    __shared__ float smf[64 * 65];
    const int t = threadIdx.x;
    const int b = blockIdx.x;
    if (b < B_SCAT) {
        // ---- scatter + gather + 4-layer ee
        float* srd = smf;                       // [4][NH*EFD] = 256
        if (t < 4 * NH * EFD) srd[t] = ((const float*)g_rede)[t];
        __syncthreads();
        const int e = b * 256 + t;
        if (e >= NE) return;
        const int pos = atomicAdd(&g_cur[dst[e]], 1);
        g_srcs[pos] = src[e];
        float r[EFD];
#pragma unroll
        for (int q = 0; q < EFD / 4; q++) {
            const float4 v = __ldg((const float4*)&ef[(size_t)e * EFD + q * 4]);
            r[q * 4 + 0] = v.x; r[q * 4 + 1] = v.y;
            r[q * 4 + 2] = v.z; r[q * 4 + 3] = v.w;
            *(float4*)&g_efs[(size_t)pos * EFD + q * 4] = v;
        }
#pragma unroll
        for (int lid = 0; lid < 4; lid++) {
            float v0 = 0.f, v1 = 0.f;
#pragma unroll
            for (int k = 0; k < EFD; k++) {
                v0 = fmaf(r[k], srd[lid * 64 + k], v0);
                v1 = fmaf(r[k], srd[lid * 64 + EFD + k], v1);
            }
            *(float2*)&g_eeall[lid][(size_t)pos * NH] = make_float2(v0, v1);
        }
    } else {
        // ---- layer-0 el/er for 64 nodes (by ORIGINAL node id)
        const int n0 = (b - B_SCAT) * 64;
        for (int i = t; i < 64 * NF; i += 256) {
            const int row = i >> 6, col = i & 63;
            const int n = n0 + row;
            smf[row * 65 + col] = (n < NN) ? x[(size_t)n * NF + col] : 0.f;
        }
        __syncthreads();
        const int type = t >> 7, h = (t >> 6) & 1, i = t & 63;
        const int n = n0 + i;
        if (n < NN) {
            const float* rd = (type ? g_redr : g_redl)[0] + h * NF;
            float v = 0.f;
#pragma unroll
            for (int k = 0; k < NF; k++) v = fmaf(smf[i * 65 + k], rd[k], v);
            (type ? g_erb : g_elb)[0][n * NH + h] = v;
        }
    }
}

// ================= fused per-layer kernel ====================================
// 256 threads, 16 sorted positions/block (degree-uniform, HEAVIEST FIRST).
// Phase A: half-warp per node, 2 edges/iter (R13 form, no prefetch).
// Phase B: 8-row x 1-col register tiles, 2 row-groups share each weight load.
// Phase C: head-mean -> hout (rows via g_perm); next-layer el/er epilogue.
#define STS_ 129                   // st row stride
__global__ __launch_bounds__(256) void layer_kernel(
        const float* __restrict__ x,
        const float* __restrict__ Wn, const float* __restrict__ We,
        const float* __restrict__ b,
        const float* __restrict__ el_in, const float* __restrict__ er_in,
        float* __restrict__ el_out, float* __restrict__ er_out,
        int lid, int last, float* __restrict__ hout)
{
    __shared__ __align__(16) float sV[192 * 16];  // [k][i]; k<128 xs(h*64+kk), k>=128 us
    __shared__ float st[16 * STS_];               // [i][c]
    __shared__ int sperm[16];

    const int t = threadIdx.x;
    const int wid = t >> 5, lane = t & 31;
    const int half = lane >> 4, s = lane & 15;
    const int i = wid * 2 + half;                 // block-local sorted slot 0..15
    const int n0 = blockIdx.x * 16;               // sorted position base
    if (t < 16) sperm[t] = g_perm[n0 + t];
    const float* eep = g_eeall[lid];

    const int n = g_perm[n0 + i];                 // actual node id
    const float2 er2 = *(const float2*)&er_in[n * NH];
    const int start = g_off[n0 + i];
    const int deg = g_off[n0 + i + 1] - start;
    const int dother = __shfl_xor_sync(0xffffffffu, deg, 16);
    const int degmax = (deg > dother) ? deg : dother;

    float4 xa0 = make_float4(0.f, 0.f, 0.f, 0.f);   // head-0 weighted x sums
    float4 xa1 = make_float4(0.f, 0.f, 0.f, 0.f);   // head-1
    float2 ua0 = make_float2(0.f, 0.f);
    float2 ua1 = make_float2(0.f, 0.f);
    float s0 = 0.f, s1 = 0.f;

    for (int jj = 0; jj < degmax; jj += 2) {
        // two edge slots, index-clamped so loads stay in-bounds
        int o0 = jj;     if (o0 > deg - 1) o0 = deg - 1; if (o0 < 0) o0 = 0;
        int o1 = jj + 1; if (o1 > deg - 1) o1 = deg - 1; if (o1 < 0) o1 = 0;
        int j0 = start + o0; if (j0 > NE - 1) j0 = NE - 1;
        int j1 = start + o1; if (j1 > NE - 1) j1 = NE - 1;
        const bool a0 = (jj < deg), a1 = (jj + 1 < deg);

        const int sn0 = g_srcs[j0], sn1 = g_srcs[j1];
        const float2 ee0 = *(const float2*)&eep[(size_t)j0 * NH];
        const float2 ee1 = *(const float2*)&eep[(size_t)j1 * NH];
        const float2 eA = *(const float2*)&el_in[sn0 * NH];
        const float2 eB = *(const float2*)&el_in[sn1 * NH];
        const float4 xv0 = __ldg((const float4*)&x[(size_t)sn0 * NF + s * 4]);
        const float4 xv1 = __ldg((const float4*)&x[(size_t)sn1 * NF + s * 4]);
        const float2 ev0 = *(const float2*)&g_efs[(size_t)j0 * EFD + s * 2];
        const float2 ev1 = *(const float2*)&g_efs[(size_t)j1 * EFD + s * 2];

        float l00 = eA.x + er2.x + ee0.x, l01 = eA.y + er2.y + ee0.y;
        float l10 = eB.x + er2.x + ee1.x, l11 = eB.y + er2.y + ee1.y;
        l00 = (l00 > 0.f) ? l00 : 0.2f * l00;
        l01 = (l01 > 0.f) ? l01 : 0.2f * l01;
        l10 = (l10 > 0.f) ? l10 : 0.2f * l10;
        l11 = (l11 > 0.f) ? l11 : 0.2f * l11;
        const float p00 = a0 ? __expf(l00) : 0.f;
        const float p01 = a0 ? __expf(l01) : 0.f;
        const float p10 = a1 ? __expf(l10) : 0.f;
        const float p11 = a1 ? __expf(l11) : 0.f;
        s0 += p00 + p10; s1 += p01 + p11;

        xa0.x = fmaf(xv0.x, p00, fmaf(xv1.x, p10, xa0.x));
        xa0.y = fmaf(xv0.y, p00, fmaf(xv1.y, p10, xa0.y));
        xa0.z = fmaf(xv0.z, p00, fmaf(xv1.z, p10, xa0.z));
        xa0.w = fmaf(xv0.w, p00, fmaf(xv1.w, p10, xa0.w));
        xa1.x = fmaf(xv0.x, p01, fmaf(xv1.x, p11, xa1.x));
        xa1.y = fmaf(xv0.y, p01, fmaf(xv1.y, p11, xa1.y));
        xa1.z = fmaf(xv0.z, p01, fmaf(xv1.z, p11, xa1.z));
        xa1.w = fmaf(xv0.w, p01, fmaf(xv1.w, p11, xa1.w));
        ua0.x = fmaf(ev0.x, p00, fmaf(ev1.x, p10, ua0.x));
        ua0.y = fmaf(ev0.y, p00, fmaf(ev1.y, p10, ua0.y));
        ua1.x = fmaf(ev0.x, p01, fmaf(ev1.x, p11, ua1.x));
        ua1.y = fmaf(ev0.y, p01, fmaf(ev1.y, p11, ua1.y));
    }

    const float inv0 = (s0 > 0.f) ? 1.f / s0 : 0.f;   // deg-0 -> msg = 0
    const float inv1 = (s1 > 0.f) ? 1.f / s1 : 0.f;
    sV[(4 * s + 0) * 16 + i] = xa0.x * inv0;
    sV[(4 * s + 1) * 16 + i] = xa0.y * inv0;
    sV[(4 * s + 2) * 16 + i] = xa0.z * inv0;
    sV[(4 * s + 3) * 16 + i] = xa0.w * inv0;
    sV[(64 + 4 * s + 0) * 16 + i] = xa1.x * inv1;
    sV[(64 + 4 * s + 1) * 16 + i] = xa1.y * inv1;
    sV[(64 + 4 * s + 2) * 16 + i] = xa1.z * inv1;
    sV[(64 + 4 * s + 3) * 16 + i] = xa1.w * inv1;
    sV[(128 + 2 * s + 0) * 16 + i] = ua0.x * inv0;
    sV[(128 + 2 * s + 1) * 16 + i] = ua0.y * inv0;
    sV[(160 + 2 * s + 0) * 16 + i] = ua1.x * inv1;
    sV[(160 + 2 * s + 1) * 16 + i] = ua1.y * inv1;
    __syncthreads();

    // -------- Phase B: 8-row x 1-col tiles; 2 row-groups --------
    {
        const int c = t & 127, h = c >> 6;
        const int rb = (t >> 7) * 8;              // row base: 0 or 8
        float acc[8];
#pragma unroll
        for (int r = 0; r < 8; r++) acc[r] = 0.f;

        const float* sVx = sV + (h * 64) * 16 + rb;
#pragma unroll 4
        for (int kk = 0; kk < NF; kk++) {
            const float w = __ldg(&Wn[kk * FH + c]);
            const float4 v0 = *(const float4*)&sVx[kk * 16];
            const float4 v1 = *(const float4*)&sVx[kk * 16 + 4];
            acc[0] = fmaf(v0.x, w, acc[0]); acc[1] = fmaf(v0.y, w, acc[1]);
            acc[2] = fmaf(v0.z, w, acc[2]); acc[3] = fmaf(v0.w, w, acc[3]);
            acc[4] = fmaf(v1.x, w, acc[4]); acc[5] = fmaf(v1.y, w, acc[5]);
            acc[6] = fmaf(v1.z, w, acc[6]); acc[7] = fmaf(v1.w, w, acc[7]);
        }
        const float* sVu = sV + (128 + h * 32) * 16 + rb;
#pragma unroll 4
        for (int kk = 0; kk < EFD; kk++) {
            const float w = __ldg(&We[kk * FH + c]);
            const float4 v0 = *(const float4*)&sVu[kk * 16];
            const float4 v1 = *(const float4*)&sVu[kk * 16 + 4];
            acc[0] = fmaf(v0.x, w, acc[0]); acc[1] = fmaf(v0.y, w, acc[1]);
            acc[2] = fmaf(v0.z, w, acc[2]); acc[3] = fmaf(v0.w, w, acc[3]);
            acc[4] = fmaf(v1.x, w, acc[4]); acc[5] = fmaf(v1.y, w, acc[5]);
            acc[6] = fmaf(v1.z, w, acc[6]); acc[7] = fmaf(v1.w, w, acc[7]);
        }
        const float bc = __ldg(&b[c]);
#pragma unroll
        for (int r = 0; r < 8; r++)
            st[(rb + r) * STS_ + c] = acc[r] + bc;
    }
    __syncthreads();

    // -------- Phase C: head mean -> hout rows via perm (4 per thread) -------
#pragma unroll
    for (int rep = 0; rep < 4; rep++) {
        const int idx = rep * 256 + t;
        const int ii = idx >> 6, d = idx & 63;
        hout[(size_t)sperm[ii] * DH + d] =
            0.5f * (st[ii * STS_ + d] + st[ii * STS_ + DH + d]);
    }
    // next-layer el/er (64 tasks: type x head x 16 nodes)
    if (!last && t < 64) {
        const int type = t >> 5, hh = (t >> 4) & 1, ii = t & 15;
        const float* rd = (type ? g_redr : g_redl)[lid + 1] + hh * NF;
        float v = 0.f;
#pragma unroll
        for (int d = 0; d < DH; d++)
            v = fmaf(0.5f * (st[ii * STS_ + d] + st[ii * STS_ + DH + d]), rd[d], v);
        (type ? er_out : el_out)[sperm[ii] * NH + hh] = v;
    }
}

// ---------------- host-side driver ------------------------------------------
extern "C" void kernel_launch(void* const* d_in, const int* in_sizes, int n_in,
                              void* d_out, int out_size)
{
    const float* x   = (const float*)d_in[0];
    const float* e   = (const float*)d_in[1];
    const int*   src = (const int*)  d_in[2];
    const int*   dst = (const int*)  d_in[3];

    // Only the LAST snapshot contributes to the output (decoded[-1]).
    const int S = in_sizes[0] / (NN * NF);
    const float* xs = x   + (size_t)(S - 1) * NN * NF;
    const float* es = e   + (size_t)(S - 1) * NE * EFD;
    const int*   ss = src + (size_t)(S - 1) * NE;
    const int*   ds = dst + (size_t)(S - 1) * NE;

    void *ph = nullptr, *ph2 = nullptr, *pwp = nullptr, *pel = nullptr, *per = nullptr;
    cudaGetSymbolAddress(&ph,  g_h);
    cudaGetSymbolAddress(&ph2, g_h2);
    cudaGetSymbolAddress(&pwp, g_Wp);
    cudaGetSymbolAddress(&pel, g_elb);
    cudaGetSymbolAddress(&per, g_erb);
    float* h  = (float*)ph;
    float* h2 = (float*)ph2;
    const float* Wp = (const float*)pwp;
    float* elb[2] = { (float*)pel, (float*)pel + NN * NH };
    float* erb[2] = { (float*)per, (float*)per + NN * NH };

    cudaFuncSetAttribute(scan_kernel, cudaFuncAttributeMaxDynamicSharedMemorySize,
                         SCAN_SMEM);

    // Input order (setup_inputs dict insertion order):
    //   0:x 1:e 2:src 3:dst, 4..9:enc0{Wn,We,al,ar,ae,b}, 10..15:enc1,
    //   16..21:dec0, 22..27:dec1, 28:W_e2d
    const float* P[29];
    for (int i = 4; i <= 28; i++) P[i] = (const float*)d_in[i];

    PrepParams pp;
    pp.Wn[0] = P[4];  pp.We[0] = P[5];  pp.al[0] = P[6];  pp.ar[0] = P[7];  pp.ae[0] = P[8];
    pp.Wn[1] = P[10]; pp.We[1] = P[11]; pp.al[1] = P[12]; pp.ar[1] = P[13]; pp.ae[1] = P[14];
    pp.Wn[2] = P[16]; pp.We[2] = P[17]; pp.al[2] = P[18]; pp.ar[2] = P[19]; pp.ae[2] = P[20];
    pp.Wn[3] = P[22]; pp.We[3] = P[23]; pp.al[3] = P[24]; pp.ar[3] = P[25]; pp.ae[3] = P[26];
    pp.We2d = P[28];

    pre1_kernel<<<B_HIST + B_WF + B_PREP, 256>>>(ds, pp);
    scan_kernel<<<1, SCAN_T, SCAN_SMEM>>>();
    pre2_kernel<<<B_SCAT + B_NA, 256>>>(ds, ss, es, xs);

    layer_kernel<<<NN / 16, 256>>>(xs, P[4],  P[5],  P[9],
                                   elb[0], erb[0], elb[1], erb[1], 0, 0, h);
    layer_kernel<<<NN / 16, 256>>>(h,  P[10], P[11], P[15],
                                   elb[1], erb[1], elb[0], erb[0], 1, 0, h2);
    layer_kernel<<<NN / 16, 256>>>(h2, Wp,    P[17], P[21],
                                   elb[0], erb[0], elb[1], erb[1], 2, 0, h);
    layer_kernel<<<NN / 16, 256>>>(h,  P[22], P[23], P[27],
                                   elb[1], erb[1], elb[0], erb[0], 3, 1, (float*)d_out);
}